// round 6
// baseline (speedup 1.0000x reference)
#include <cuda_runtime.h>

typedef unsigned long long ull;

#define B_DIM    128
#define IN_DIM   1024
#define OUT_DIM  1024
#define KSPLIT   16
#define K_CHUNK  64        // == K_PER_CTA, single smem stage
#define O_TILE   128
#define THREADS  512
#define GRID     (KSPLIT * (OUT_DIM / O_TILE))   // 128 CTAs, one wave

#define SMEM_BYTES (K_CHUNK * B_DIM * 8 + K_CHUNK * O_TILE * 4)   // 96 KB

// 8 MB fp32 partial sums: g_part[ks][b][o]
__device__ float g_part[KSPLIT * B_DIM * OUT_DIM];
__device__ unsigned int g_ctr;   // zero-init; monotonic across replays

__device__ __forceinline__ ull fma2(ull a, ull b, ull c) {
    ull d;
    asm("fma.rn.f32x2 %0, %1, %2, %3;" : "=l"(d) : "l"(a), "l"(b), "l"(c));
    return d;
}
__device__ __forceinline__ ull dup2(float w) {
    unsigned u = __float_as_uint(w);
    ull d;
    asm("mov.b64 %0, {%1, %1};" : "=l"(d) : "r"(u));
    return d;
}
__device__ __forceinline__ float lo32(ull v) { return __uint_as_float((unsigned)v); }
__device__ __forceinline__ float hi32(ull v) { return __uint_as_float((unsigned)(v >> 32)); }

// ---------------------------------------------------------------------------
// Fused persistent kernel. grid 128 = 16 k-splits x 8 o-tiles, 512 threads.
// Microtile 4b x 8o. Inner iter: 4 LDS.128 + 16 FFMA2, no MOVs.
//   - acc packs o-PAIRS -> w read as naturally contiguous f32x2 from wsf
//   - x pre-duplicated in smem (xsd: ull {x,x}) -> broadcast operand, dup free
// ---------------------------------------------------------------------------
__global__ void __launch_bounds__(THREADS, 1)
sic_fused(const float* __restrict__ x, const float* __restrict__ means,
          const float* __restrict__ bias, const int* __restrict__ dest,
          float* __restrict__ out)
{
    extern __shared__ __align__(16) ull smem_raw[];
    ull*   xsd = smem_raw;                             // [kk][b] dup, 64x128 ull (64 KB)
    float* wsf = (float*)(smem_raw + K_CHUNK * B_DIM); // [kk][o],    64x128 f   (32 KB)

    const int tid = threadIdx.x;
    const int ks  = blockIdx.x & (KSPLIT - 1);
    const int o0  = (blockIdx.x >> 4) * O_TILE;
    const int k0  = ks * K_CHUNK;

    // ---- x chunk -> xsd (transposed, duplicated, 16B-chunk swizzled) ----
    for (int s = tid; s < B_DIM * (K_CHUNK / 4); s += THREADS) {
        const int b  = s >> 4;                 // K_CHUNK/4 = 16 items per b
        const int kv = (s & 15) << 2;
        const float4 v = *reinterpret_cast<const float4*>(x + b * IN_DIM + k0 + kv);
        const int bh = b >> 1, bl = b & 1;
        xsd[(kv + 0) * B_DIM + ((((bh ^ (kv + 0)) & 63) << 1) | bl)] = dup2(v.x);
        xsd[(kv + 1) * B_DIM + ((((bh ^ (kv + 1)) & 63) << 1) | bl)] = dup2(v.y);
        xsd[(kv + 2) * B_DIM + ((((bh ^ (kv + 2)) & 63) << 1) | bl)] = dup2(v.z);
        xsd[(kv + 3) * B_DIM + ((((bh ^ (kv + 3)) & 63) << 1) | bl)] = dup2(v.w);
    }
    // ---- W gather: wsf[kk][o] = means[dest[(o0+o)*IN + k0+kk]] ----
    // o fixed per item -> 4 means reads hit one 64B line (L1-friendly).
    for (int s = tid; s < O_TILE * (K_CHUNK / 4); s += THREADS) {
        const int o  = s & 127;
        const int kv = (s >> 7) << 2;
        const int4 dd = *reinterpret_cast<const int4*>(
            dest + (size_t)(o0 + o) * IN_DIM + k0 + kv);
        const int oh = o >> 2, ol = o & 3;
        wsf[(kv + 0) * O_TILE + ((((oh ^ (kv + 0)) & 31) << 2) | ol)] = means[dd.x];
        wsf[(kv + 1) * O_TILE + ((((oh ^ (kv + 1)) & 31) << 2) | ol)] = means[dd.y];
        wsf[(kv + 2) * O_TILE + ((((oh ^ (kv + 2)) & 31) << 2) | ol)] = means[dd.z];
        wsf[(kv + 3) * O_TILE + ((((oh ^ (kv + 3)) & 31) << 2) | ol)] = means[dd.w];
    }
    __syncthreads();

    const int oc = tid & 15;    // outputs oc*8 .. oc*8+7
    const int bc = tid >> 4;    // batches bc*4 .. bc*4+3  (0..31)

    ull acc[16];   // acc[bi*4+op]: batch bc*4+bi, outputs (oc*8+2op, +1)
#pragma unroll
    for (int i = 0; i < 16; i++) acc[i] = 0ull;

    // ---- main loop: 4 LDS.128 + 16 FFMA2 per iter ----
#pragma unroll 8
    for (int kk = 0; kk < K_CHUNK; kk++) {
        const float* wrow = wsf + kk * O_TILE;
        const ull*   xrow = xsd + kk * B_DIM;
        const ulonglong2 w01 = *reinterpret_cast<const ulonglong2*>(
            wrow + (((((oc << 1)    ) ^ kk) & 31) << 2));   // outputs oc*8..+3
        const ulonglong2 w23 = *reinterpret_cast<const ulonglong2*>(
            wrow + (((((oc << 1) | 1) ^ kk) & 31) << 2));   // outputs oc*8+4..+7
        const ulonglong2 x0 = *reinterpret_cast<const ulonglong2*>(
            xrow + (((((bc << 1)    ) ^ kk) & 63) << 1));   // batches bc*4, +1 (dup)
        const ulonglong2 x1 = *reinterpret_cast<const ulonglong2*>(
            xrow + (((((bc << 1) | 1) ^ kk) & 63) << 1));   // batches bc*4+2, +3
        acc[0]  = fma2(x0.x, w01.x, acc[0]);
        acc[1]  = fma2(x0.x, w01.y, acc[1]);
        acc[2]  = fma2(x0.x, w23.x, acc[2]);
        acc[3]  = fma2(x0.x, w23.y, acc[3]);
        acc[4]  = fma2(x0.y, w01.x, acc[4]);
        acc[5]  = fma2(x0.y, w01.y, acc[5]);
        acc[6]  = fma2(x0.y, w23.x, acc[6]);
        acc[7]  = fma2(x0.y, w23.y, acc[7]);
        acc[8]  = fma2(x1.x, w01.x, acc[8]);
        acc[9]  = fma2(x1.x, w01.y, acc[9]);
        acc[10] = fma2(x1.x, w23.x, acc[10]);
        acc[11] = fma2(x1.x, w23.y, acc[11]);
        acc[12] = fma2(x1.y, w01.x, acc[12]);
        acc[13] = fma2(x1.y, w01.y, acc[13]);
        acc[14] = fma2(x1.y, w23.x, acc[14]);
        acc[15] = fma2(x1.y, w23.y, acc[15]);
    }

    // ---- partials: per batch row, 2 contiguous float4 (o..o+7) ----
    {
        float* base = g_part + ((size_t)(ks * B_DIM + bc * 4)) * OUT_DIM + o0 + oc * 8;
#pragma unroll
        for (int bi = 0; bi < 4; bi++) {
            float4 f0, f1;
            f0.x = lo32(acc[bi*4+0]); f0.y = hi32(acc[bi*4+0]);
            f0.z = lo32(acc[bi*4+1]); f0.w = hi32(acc[bi*4+1]);
            f1.x = lo32(acc[bi*4+2]); f1.y = hi32(acc[bi*4+2]);
            f1.z = lo32(acc[bi*4+3]); f1.w = hi32(acc[bi*4+3]);
            *reinterpret_cast<float4*>(base + (size_t)bi * OUT_DIM)     = f0;
            *reinterpret_cast<float4*>(base + (size_t)bi * OUT_DIM + 4) = f1;
        }
    }

    // ---- device-wide barrier (monotonic counter: replay-safe) ----
    __threadfence();
    __syncthreads();
    if (tid == 0) {
        const unsigned val    = atomicAdd(&g_ctr, 1u) + 1u;
        const unsigned target = ((val - 1u) / GRID + 1u) * GRID;
        while (*(volatile unsigned*)&g_ctr < target) { }
    }
    __syncthreads();
    __threadfence();

    // ---- reduce: 65536 threads x float2; partials are L2-hot ----
    {
        const int gid = blockIdx.x * THREADS + tid;        // 0..65535
        const int off = gid * 2;                           // b*1024 + o
        const int o   = off & (OUT_DIM - 1);
        float2 a = make_float2(0.f, 0.f);
#pragma unroll
        for (int k = 0; k < KSPLIT; k++) {
            const float2 v = *reinterpret_cast<const float2*>(
                g_part + (size_t)k * (B_DIM * OUT_DIM) + off);
            a.x += v.x; a.y += v.y;
        }
        const float2 bb = *reinterpret_cast<const float2*>(bias + o);
        a.x += bb.x; a.y += bb.y;
        *reinterpret_cast<float2*>(out + off) = a;
    }
}

extern "C" void kernel_launch(void* const* d_in, const int* in_sizes, int n_in,
                              void* d_out, int out_size)
{
    (void)in_sizes; (void)n_in; (void)out_size;
    const float* x     = (const float*)d_in[0];   // [128,1024] f32
    const float* means = (const float*)d_in[1];   // [1024,16]  f32
    const float* bias  = (const float*)d_in[2];   // [1024]     f32
    // d_in[3] = col_idx (identity layout per row; unused)
    const int*   dest  = (const int*)d_in[4];     // [1024*1024] i32

    cudaFuncSetAttribute(sic_fused, cudaFuncAttributeMaxDynamicSharedMemorySize,
                         SMEM_BYTES);
    sic_fused<<<GRID, THREADS, SMEM_BYTES>>>(x, means, bias, dest, (float*)d_out);
}

// round 8
// speedup vs baseline: 1.5810x; 1.5810x over previous
#include <cuda_runtime.h>
#include <cuda_bf16.h>
#include <cstdint>
#include <cstring>

typedef unsigned long long ull;

#define B_DIM    128
#define IN_DIM   1024
#define OUT_DIM  1024
#define KSPLIT   8
#define K_TILE   128
#define N_TILE   64
#define THREADS  256
#define GRID     (KSPLIT * (OUT_DIM / N_TILE))   // 128 CTAs, one wave

#define K_PAD    136                              // bf16 elems/row; 272B stride
#define XS_HI    0
#define XS_LO    (B_DIM * K_PAD * 2)              // 34816
#define WS_HI    (2 * B_DIM * K_PAD * 2)          // 69632
#define WS_LO    (WS_HI + N_TILE * K_PAD * 2)     // 87040
#define SMEM_BYTES (WS_LO + N_TILE * K_PAD * 2)   // 104448

// 4 MB fp32 partials g_part[ks][b][o] + replay-safe barrier counter
__device__ float g_part[KSPLIT * B_DIM * OUT_DIM];
__device__ unsigned g_ctr;

__device__ __forceinline__ uint32_t smem_u32(const void* p) {
    uint32_t a;
    asm("{ .reg .u64 t; cvta.to.shared.u64 t, %1; cvt.u32.u64 %0, t; }"
        : "=r"(a) : "l"(p));
    return a;
}
__device__ __forceinline__ uint32_t bf2u(__nv_bfloat162 v) {
    uint32_t u; memcpy(&u, &v, 4); return u;
}

#define LDSM_X4(r0, r1, r2, r3, addr)                                       \
    asm volatile("ldmatrix.sync.aligned.m8n8.x4.shared.b16 {%0,%1,%2,%3}, [%4];" \
                 : "=r"(r0), "=r"(r1), "=r"(r2), "=r"(r3) : "r"(addr))

#define MMA_BF16(c, a0, a1, a2, a3, b0, b1)                                 \
    asm volatile("mma.sync.aligned.m16n8k16.row.col.f32.bf16.bf16.f32 "     \
                 "{%0,%1,%2,%3}, {%4,%5,%6,%7}, {%8,%9}, {%0,%1,%2,%3};"    \
                 : "+f"((c)[0]), "+f"((c)[1]), "+f"((c)[2]), "+f"((c)[3])   \
                 : "r"(a0), "r"(a1), "r"(a2), "r"(a3), "r"(b0), "r"(b1))

// ---------------------------------------------------------------------------
// Fused: stage x & gathered W as bf16 hi/lo in smem -> mma.sync 3-pass
// (hi*hi + lo*hi + hi*lo, fp32 acc) -> partials -> barrier -> reduce + bias.
// ---------------------------------------------------------------------------
__global__ void __launch_bounds__(THREADS, 1)
sic_mma(const float* __restrict__ x, const float* __restrict__ means,
        const float* __restrict__ bias, const int* __restrict__ dest,
        float* __restrict__ out)
{
    extern __shared__ __align__(16) char smem[];
    const uint32_t sb = smem_u32(smem);
    const int tid = threadIdx.x;
    const int wid = tid >> 5, lid = tid & 31;
    const int ks  = blockIdx.x & (KSPLIT - 1);
    const int o0  = (blockIdx.x >> 3) * N_TILE;
    const int k0  = ks * K_TILE;

    // ---- stage x slice [128 x 128] -> bf16 hi/lo, rows padded to K_PAD ----
    for (int idx = tid; idx < B_DIM * (K_TILE / 4); idx += THREADS) {
        const int row = idx >> 5;
        const int k   = (idx & 31) << 2;
        const float4 v = *reinterpret_cast<const float4*>(x + (size_t)row * IN_DIM + k0 + k);
        const __nv_bfloat16 hx = __float2bfloat16(v.x), hy = __float2bfloat16(v.y);
        const __nv_bfloat16 hz = __float2bfloat16(v.z), hw = __float2bfloat16(v.w);
        uint2 hi, lo;
        hi.x = bf2u(__nv_bfloat162(hx, hy));
        hi.y = bf2u(__nv_bfloat162(hz, hw));
        lo.x = bf2u(__floats2bfloat162_rn(v.x - __bfloat162float(hx),
                                          v.y - __bfloat162float(hy)));
        lo.y = bf2u(__floats2bfloat162_rn(v.z - __bfloat162float(hz),
                                          v.w - __bfloat162float(hw)));
        const uint32_t byte = (uint32_t)row * (K_PAD * 2) + k * 2;
        *reinterpret_cast<uint2*>(smem + XS_HI + byte) = hi;
        *reinterpret_cast<uint2*>(smem + XS_LO + byte) = lo;
    }
    // ---- gather W tile [64 x 128]: means[dest[...]] -> bf16 hi/lo ----
    for (int idx = tid; idx < N_TILE * (K_TILE / 4); idx += THREADS) {
        const int o = idx >> 5;
        const int k = (idx & 31) << 2;
        const int4 dd = *reinterpret_cast<const int4*>(
            dest + (size_t)(o0 + o) * IN_DIM + k0 + k);
        const float m0 = means[dd.x], m1 = means[dd.y];
        const float m2 = means[dd.z], m3 = means[dd.w];
        const __nv_bfloat16 h0 = __float2bfloat16(m0), h1 = __float2bfloat16(m1);
        const __nv_bfloat16 h2 = __float2bfloat16(m2), h3 = __float2bfloat16(m3);
        uint2 hi, lo;
        hi.x = bf2u(__nv_bfloat162(h0, h1));
        hi.y = bf2u(__nv_bfloat162(h2, h3));
        lo.x = bf2u(__floats2bfloat162_rn(m0 - __bfloat162float(h0),
                                          m1 - __bfloat162float(h1)));
        lo.y = bf2u(__floats2bfloat162_rn(m2 - __bfloat162float(h2),
                                          m3 - __bfloat162float(h3)));
        const uint32_t byte = (uint32_t)o * (K_PAD * 2) + k * 2;
        *reinterpret_cast<uint2*>(smem + WS_HI + byte) = hi;
        *reinterpret_cast<uint2*>(smem + WS_LO + byte) = lo;
    }
    __syncthreads();

    // ---- mma.sync mainloop: warp owns 16 batches x 64 outputs ----
    const int m0 = wid * 16;
    float acc[8][4];
#pragma unroll
    for (int n = 0; n < 8; n++)
#pragma unroll
        for (int i = 0; i < 4; i++) acc[n][i] = 0.f;

    // ldmatrix lane addresses.
    // A (x4, per k-step s): row m0+(l&15), col s*16 + (l>>4)*8
    const uint32_t a_row  = (uint32_t)(m0 + (lid & 15)) * (K_PAD * 2);
    const uint32_t a_coff = (uint32_t)(lid >> 4) * 16;          // bytes
    // B (x4, per k-pair kp, n-tile n): row n*8+(l&7), col kp*32 + (l>>3)*8
    const uint32_t b_row  = (uint32_t)(lid & 7) * (K_PAD * 2);
    const uint32_t b_coff = (uint32_t)(lid >> 3) * 16;          // bytes

#pragma unroll
    for (int kp = 0; kp < 4; kp++) {                 // k-step pairs: k = kp*32
        uint32_t ah0[4], ah1[4], al0[4], al1[4];
        {
            const uint32_t c0 = (uint32_t)(kp * 64) + a_coff;        // kstep 2kp
            const uint32_t c1 = c0 + 32;                             // kstep 2kp+1
            LDSM_X4(ah0[0], ah0[1], ah0[2], ah0[3], sb + XS_HI + a_row + c0);
            LDSM_X4(ah1[0], ah1[1], ah1[2], ah1[3], sb + XS_HI + a_row + c1);
            LDSM_X4(al0[0], al0[1], al0[2], al0[3], sb + XS_LO + a_row + c0);
            LDSM_X4(al1[0], al1[1], al1[2], al1[3], sb + XS_LO + a_row + c1);
        }
#pragma unroll
        for (int n = 0; n < 8; n++) {
            const uint32_t bbase = (uint32_t)(n * 8) * (K_PAD * 2)
                                 + (uint32_t)(kp * 64) + b_coff;
            uint32_t bh[4], bl[4];
            LDSM_X4(bh[0], bh[1], bh[2], bh[3], sb + WS_HI + b_row + bbase);
            LDSM_X4(bl[0], bl[1], bl[2], bl[3], sb + WS_LO + b_row + bbase);
            // kstep 2kp   : B frags {bh[0], bh[1]}
            MMA_BF16(acc[n], ah0[0], ah0[1], ah0[2], ah0[3], bh[0], bh[1]);
            MMA_BF16(acc[n], al0[0], al0[1], al0[2], al0[3], bh[0], bh[1]);
            MMA_BF16(acc[n], ah0[0], ah0[1], ah0[2], ah0[3], bl[0], bl[1]);
            // kstep 2kp+1 : B frags {bh[2], bh[3]}
            MMA_BF16(acc[n], ah1[0], ah1[1], ah1[2], ah1[3], bh[2], bh[3]);
            MMA_BF16(acc[n], al1[0], al1[1], al1[2], al1[3], bh[2], bh[3]);
            MMA_BF16(acc[n], ah1[0], ah1[1], ah1[2], ah1[3], bl[2], bl[3]);
        }
    }

    // ---- write partials: D[g][2tg..] per fragment layout ----
    {
        const int g  = lid >> 2;            // 0..7
        const int tg = lid & 3;             // 0..3
        float* r0 = g_part + ((size_t)(ks * B_DIM + m0 + g))     * OUT_DIM + o0 + 2 * tg;
        float* r1 = g_part + ((size_t)(ks * B_DIM + m0 + g + 8)) * OUT_DIM + o0 + 2 * tg;
#pragma unroll
        for (int n = 0; n < 8; n++) {
            *reinterpret_cast<float2*>(r0 + n * 8) = make_float2(acc[n][0], acc[n][1]);
            *reinterpret_cast<float2*>(r1 + n * 8) = make_float2(acc[n][2], acc[n][3]);
        }
    }

    // ---- device-wide barrier (monotonic counter: replay-safe) ----
    __threadfence();
    __syncthreads();
    if (tid == 0) {
        const unsigned val    = atomicAdd(&g_ctr, 1u) + 1u;
        const unsigned target = ((val - 1u) / GRID + 1u) * GRID;
        while (*(volatile unsigned*)&g_ctr < target) { }
    }
    __syncthreads();
    __threadfence();

    // ---- reduce: 32768 threads x float4 (exactly covers 128x1024) ----
    {
        const int gid = blockIdx.x * THREADS + tid;
        const int off = gid * 4;
        const int o   = off & (OUT_DIM - 1);
        float4 a = make_float4(0.f, 0.f, 0.f, 0.f);
#pragma unroll
        for (int k = 0; k < KSPLIT; k++) {
            const float4 v = *reinterpret_cast<const float4*>(
                g_part + (size_t)k * (B_DIM * OUT_DIM) + off);
            a.x += v.x; a.y += v.y; a.z += v.z; a.w += v.w;
        }
        const float4 bb = *reinterpret_cast<const float4*>(bias + o);
        a.x += bb.x; a.y += bb.y; a.z += bb.z; a.w += bb.w;
        *reinterpret_cast<float4*>(out + off) = a;
    }
}

extern "C" void kernel_launch(void* const* d_in, const int* in_sizes, int n_in,
                              void* d_out, int out_size)
{
    (void)in_sizes; (void)n_in; (void)out_size;
    const float* x     = (const float*)d_in[0];   // [128,1024] f32
    const float* means = (const float*)d_in[1];   // [1024,16]  f32
    const float* bias  = (const float*)d_in[2];   // [1024]     f32
    // d_in[3] = col_idx (identity layout per row; unused)
    const int*   dest  = (const int*)d_in[4];     // [1024*1024] i32

    cudaFuncSetAttribute(sic_mma, cudaFuncAttributeMaxDynamicSharedMemorySize,
                         SMEM_BYTES);
    sic_mma<<<GRID, THREADS, SMEM_BYTES>>>(x, means, bias, dest, (float*)d_out);
}

// round 10
// speedup vs baseline: 1.6973x; 1.0736x over previous
#include <cuda_runtime.h>
#include <cuda_bf16.h>
#include <cstdint>
#include <cstring>

typedef unsigned long long ull;

#define B_DIM    128
#define IN_DIM   1024
#define OUT_DIM  1024
#define KSPLIT   8
#define K_TILE   128
#define N_TILE   64
#define THREADS  512
#define GRID     (KSPLIT * (OUT_DIM / N_TILE))   // 128 CTAs, one wave

#define K_PAD    136                              // bf16 elems/row; 272B stride
#define XS_HI    0
#define XS_LO    (B_DIM * K_PAD * 2)              // 34816
#define WS_HI    (2 * B_DIM * K_PAD * 2)          // 69632
#define WS_LO    (WS_HI + N_TILE * K_PAD * 2)     // 87040
#define SMEM_BYTES (WS_LO + N_TILE * K_PAD * 2)   // 104448

// 4 MB fp32 partials g_part[ks][b][o]; per-o-tile completion counters
__device__ float g_part[KSPLIT * B_DIM * OUT_DIM];
__device__ unsigned g_done[OUT_DIM / N_TILE];     // monotonic, replay-safe

__device__ __forceinline__ uint32_t smem_u32(const void* p) {
    uint32_t a;
    asm("{ .reg .u64 t; cvta.to.shared.u64 t, %1; cvt.u32.u64 %0, t; }"
        : "=r"(a) : "l"(p));
    return a;
}
__device__ __forceinline__ uint32_t bf2u(__nv_bfloat162 v) {
    uint32_t u; memcpy(&u, &v, 4); return u;
}

#define LDSM_X4(r0, r1, r2, r3, addr)                                       \
    asm volatile("ldmatrix.sync.aligned.m8n8.x4.shared.b16 {%0,%1,%2,%3}, [%4];" \
                 : "=r"(r0), "=r"(r1), "=r"(r2), "=r"(r3) : "r"(addr))

#define MMA_BF16(c, a0, a1, a2, a3, b0, b1)                                 \
    asm volatile("mma.sync.aligned.m16n8k16.row.col.f32.bf16.bf16.f32 "     \
                 "{%0,%1,%2,%3}, {%4,%5,%6,%7}, {%8,%9}, {%0,%1,%2,%3};"    \
                 : "+f"((c)[0]), "+f"((c)[1]), "+f"((c)[2]), "+f"((c)[3])   \
                 : "r"(a0), "r"(a1), "r"(a2), "r"(a3), "r"(b0), "r"(b1))

// ---------------------------------------------------------------------------
// Fused: stage x & gathered W as bf16 hi/lo -> mma.sync 3-pass (fp32 acc)
// -> partials -> per-o-tile counter; 8th arriver reduces its tile + bias.
// 16 warps: warp w = batches (w&7)*16..+15, output half (w>>3)*32..+31.
// ---------------------------------------------------------------------------
__global__ void __launch_bounds__(THREADS, 1)
sic_mma(const float* __restrict__ x, const float* __restrict__ means,
        const float* __restrict__ bias, const int* __restrict__ dest,
        float* __restrict__ out)
{
    extern __shared__ __align__(16) char smem[];
    __shared__ int s_red;
    const uint32_t sb = smem_u32(smem);
    const int tid = threadIdx.x;
    const int wid = tid >> 5, lid = tid & 31;
    const int ks  = blockIdx.x & (KSPLIT - 1);
    const int oy  = blockIdx.x >> 3;
    const int o0  = oy * N_TILE;
    const int k0  = ks * K_TILE;

    // ---- stage x slice [128 x 128] -> bf16 hi/lo, rows padded to K_PAD ----
    for (int idx = tid; idx < B_DIM * (K_TILE / 4); idx += THREADS) {
        const int row = idx >> 5;
        const int k   = (idx & 31) << 2;
        const float4 v = *reinterpret_cast<const float4*>(x + (size_t)row * IN_DIM + k0 + k);
        const __nv_bfloat16 hx = __float2bfloat16(v.x), hy = __float2bfloat16(v.y);
        const __nv_bfloat16 hz = __float2bfloat16(v.z), hw = __float2bfloat16(v.w);
        uint2 hi, lo;
        hi.x = bf2u(__nv_bfloat162(hx, hy));
        hi.y = bf2u(__nv_bfloat162(hz, hw));
        lo.x = bf2u(__floats2bfloat162_rn(v.x - __bfloat162float(hx),
                                          v.y - __bfloat162float(hy)));
        lo.y = bf2u(__floats2bfloat162_rn(v.z - __bfloat162float(hz),
                                          v.w - __bfloat162float(hw)));
        const uint32_t byte = (uint32_t)row * (K_PAD * 2) + k * 2;
        *reinterpret_cast<uint2*>(smem + XS_HI + byte) = hi;
        *reinterpret_cast<uint2*>(smem + XS_LO + byte) = lo;
    }
    // ---- gather W tile [64 x 128]: means[dest[...]] -> bf16 hi/lo ----
    for (int idx = tid; idx < N_TILE * (K_TILE / 4); idx += THREADS) {
        const int o = idx >> 5;
        const int k = (idx & 31) << 2;
        const int4 dd = *reinterpret_cast<const int4*>(
            dest + (size_t)(o0 + o) * IN_DIM + k0 + k);
        const float m0 = means[dd.x], m1 = means[dd.y];
        const float m2 = means[dd.z], m3 = means[dd.w];
        const __nv_bfloat16 h0 = __float2bfloat16(m0), h1 = __float2bfloat16(m1);
        const __nv_bfloat16 h2 = __float2bfloat16(m2), h3 = __float2bfloat16(m3);
        uint2 hi, lo;
        hi.x = bf2u(__nv_bfloat162(h0, h1));
        hi.y = bf2u(__nv_bfloat162(h2, h3));
        lo.x = bf2u(__floats2bfloat162_rn(m0 - __bfloat162float(h0),
                                          m1 - __bfloat162float(h1)));
        lo.y = bf2u(__floats2bfloat162_rn(m2 - __bfloat162float(h2),
                                          m3 - __bfloat162float(h3)));
        const uint32_t byte = (uint32_t)o * (K_PAD * 2) + k * 2;
        *reinterpret_cast<uint2*>(smem + WS_HI + byte) = hi;
        *reinterpret_cast<uint2*>(smem + WS_LO + byte) = lo;
    }
    __syncthreads();

    // ---- mma.sync mainloop: warp = 16 batches x 32 outputs ----
    const int m0 = (wid & 7) * 16;
    const int nh = wid >> 3;               // output half: nh*32
    float acc[4][4];
#pragma unroll
    for (int n = 0; n < 4; n++)
#pragma unroll
        for (int i = 0; i < 4; i++) acc[n][i] = 0.f;

    const uint32_t a_row  = (uint32_t)(m0 + (lid & 15)) * (K_PAD * 2);
    const uint32_t a_coff = (uint32_t)(lid >> 4) * 16;
    const uint32_t b_row  = (uint32_t)(lid & 7) * (K_PAD * 2);
    const uint32_t b_coff = (uint32_t)(lid >> 3) * 16;

#pragma unroll
    for (int kp = 0; kp < 4; kp++) {                 // k-step pairs: k = kp*32
        uint32_t ah0[4], ah1[4], al0[4], al1[4];
        {
            const uint32_t c0 = (uint32_t)(kp * 64) + a_coff;
            const uint32_t c1 = c0 + 32;
            LDSM_X4(ah0[0], ah0[1], ah0[2], ah0[3], sb + XS_HI + a_row + c0);
            LDSM_X4(ah1[0], ah1[1], ah1[2], ah1[3], sb + XS_HI + a_row + c1);
            LDSM_X4(al0[0], al0[1], al0[2], al0[3], sb + XS_LO + a_row + c0);
            LDSM_X4(al1[0], al1[1], al1[2], al1[3], sb + XS_LO + a_row + c1);
        }
#pragma unroll
        for (int n = 0; n < 4; n++) {
            const uint32_t bbase = (uint32_t)((nh * 4 + n) * 8) * (K_PAD * 2)
                                 + (uint32_t)(kp * 64) + b_coff;
            uint32_t bh[4], bl[4];
            LDSM_X4(bh[0], bh[1], bh[2], bh[3], sb + WS_HI + b_row + bbase);
            LDSM_X4(bl[0], bl[1], bl[2], bl[3], sb + WS_LO + b_row + bbase);
            MMA_BF16(acc[n], ah0[0], ah0[1], ah0[2], ah0[3], bh[0], bh[1]);
            MMA_BF16(acc[n], al0[0], al0[1], al0[2], al0[3], bh[0], bh[1]);
            MMA_BF16(acc[n], ah0[0], ah0[1], ah0[2], ah0[3], bl[0], bl[1]);
            MMA_BF16(acc[n], ah1[0], ah1[1], ah1[2], ah1[3], bh[2], bh[3]);
            MMA_BF16(acc[n], al1[0], al1[1], al1[2], al1[3], bh[2], bh[3]);
            MMA_BF16(acc[n], ah1[0], ah1[1], ah1[2], ah1[3], bl[2], bl[3]);
        }
    }

    // ---- write partials ----
    {
        const int g  = lid >> 2;
        const int tg = lid & 3;
        float* r0 = g_part + ((size_t)(ks * B_DIM + m0 + g))     * OUT_DIM
                  + o0 + nh * 32 + 2 * tg;
        float* r1 = g_part + ((size_t)(ks * B_DIM + m0 + g + 8)) * OUT_DIM
                  + o0 + nh * 32 + 2 * tg;
#pragma unroll
        for (int n = 0; n < 4; n++) {
            *reinterpret_cast<float2*>(r0 + n * 8) = make_float2(acc[n][0], acc[n][1]);
            *reinterpret_cast<float2*>(r1 + n * 8) = make_float2(acc[n][2], acc[n][3]);
        }
    }

    // ---- per-o-tile completion: 8th arriver reduces this tile ----
    __threadfence();
    __syncthreads();
    if (tid == 0) {
        const unsigned v = atomicAdd(&g_done[oy], 1u) + 1u;
        s_red = ((v & 7u) == 0u) ? 1 : 0;    // exactly one per tile per launch
    }
    __syncthreads();
    if (s_red) {
        __threadfence();                      // pair with producers' fences
        for (int idx = tid; idx < B_DIM * (N_TILE / 2); idx += THREADS) {
            const int b  = idx >> 5;
            const int oo = (idx & 31) * 2;
            const float* p = g_part + (size_t)b * OUT_DIM + o0 + oo;
            float2 a = make_float2(0.f, 0.f);
#pragma unroll
            for (int k = 0; k < KSPLIT; k++) {
                const float2 v = *reinterpret_cast<const float2*>(
                    p + (size_t)k * (B_DIM * OUT_DIM));
                a.x += v.x; a.y += v.y;
            }
            const float2 bb = *reinterpret_cast<const float2*>(bias + o0 + oo);
            a.x += bb.x; a.y += bb.y;
            *reinterpret_cast<float2*>(out + (size_t)b * OUT_DIM + o0 + oo) = a;
        }
    }
}

extern "C" void kernel_launch(void* const* d_in, const int* in_sizes, int n_in,
                              void* d_out, int out_size)
{
    (void)in_sizes; (void)n_in; (void)out_size;
    const float* x     = (const float*)d_in[0];   // [128,1024] f32
    const float* means = (const float*)d_in[1];   // [1024,16]  f32
    const float* bias  = (const float*)d_in[2];   // [1024]     f32
    // d_in[3] = col_idx (identity layout per row; unused)
    const int*   dest  = (const int*)d_in[4];     // [1024*1024] i32

    cudaFuncSetAttribute(sic_mma, cudaFuncAttributeMaxDynamicSharedMemorySize,
                         SMEM_BYTES);
    sic_mma<<<GRID, THREADS, SMEM_BYTES>>>(x, means, bias, dest, (float*)d_out);
}

// round 11
// speedup vs baseline: 1.7735x; 1.0449x over previous
#include <cuda_runtime.h>
#include <cuda_bf16.h>
#include <cstdint>
#include <cstring>

typedef unsigned long long ull;

#define B_DIM    128
#define IN_DIM   1024
#define OUT_DIM  1024
#define KSPLIT   8
#define K_TILE   128
#define N_TILE   64
#define THREADS  512
#define GRID     (KSPLIT * (OUT_DIM / N_TILE))   // 128 CTAs, one wave

#define K_PAD    136                              // bf16 elems/row; 272B stride
#define ROW_B    (K_PAD * 2)                      // 272
#define XS_HI    0
#define XS_LO    (B_DIM * ROW_B)                  // 34816
#define WS_HI    (2 * B_DIM * ROW_B)              // 69632
#define WS_LO    (WS_HI + N_TILE * ROW_B)         // 87040
#define SMEM_BYTES (WS_LO + N_TILE * ROW_B)       // 104448

// preconverted operands + partials + per-o-tile counters (all static device mem)
__device__ __align__(16) unsigned short g_xhi[B_DIM * IN_DIM];   // 256 KB
__device__ __align__(16) unsigned short g_xlo[B_DIM * IN_DIM];   // 256 KB
__device__ __align__(16) unsigned       g_mhl[OUT_DIM * 16];     // 64 KB: hi | lo<<16
__device__ float g_part[KSPLIT * B_DIM * OUT_DIM];               // 4 MB
__device__ unsigned g_done[OUT_DIM / N_TILE];                    // monotonic

__device__ __forceinline__ uint32_t smem_u32(const void* p) {
    uint32_t a;
    asm("{ .reg .u64 t; cvta.to.shared.u64 t, %1; cvt.u32.u64 %0, t; }"
        : "=r"(a) : "l"(p));
    return a;
}
__device__ __forceinline__ uint32_t bf2u(__nv_bfloat162 v) {
    uint32_t u; memcpy(&u, &v, 4); return u;
}
__device__ __forceinline__ unsigned short bfbits(__nv_bfloat16 v) {
    unsigned short u; memcpy(&u, &v, 2); return u;
}

#define CP_ASYNC16(sa, gp) \
    asm volatile("cp.async.ca.shared.global [%0], [%1], 16;" :: "r"(sa), "l"(gp))
#define CP_COMMIT() asm volatile("cp.async.commit_group;" ::: "memory")
#define CP_WAIT0()  asm volatile("cp.async.wait_group 0;" ::: "memory")

#define LDSM_X4(r0, r1, r2, r3, addr)                                       \
    asm volatile("ldmatrix.sync.aligned.m8n8.x4.shared.b16 {%0,%1,%2,%3}, [%4];" \
                 : "=r"(r0), "=r"(r1), "=r"(r2), "=r"(r3) : "r"(addr))

#define MMA_BF16(c, a0, a1, a2, a3, b0, b1)                                 \
    asm volatile("mma.sync.aligned.m16n8k16.row.col.f32.bf16.bf16.f32 "     \
                 "{%0,%1,%2,%3}, {%4,%5,%6,%7}, {%8,%9}, {%0,%1,%2,%3};"    \
                 : "+f"((c)[0]), "+f"((c)[1]), "+f"((c)[2]), "+f"((c)[3])   \
                 : "r"(a0), "r"(a1), "r"(a2), "r"(a3), "r"(b0), "r"(b1))

// ---------------------------------------------------------------------------
// Prep: x -> bf16 hi/lo planes (once, not 16x); means -> packed hi|lo u32.
// ---------------------------------------------------------------------------
__global__ void __launch_bounds__(256)
sic_prep(const float* __restrict__ x, const float* __restrict__ means)
{
    const int idx = blockIdx.x * 256 + threadIdx.x;      // 0..32767
    const float4 v = reinterpret_cast<const float4*>(x)[idx];
    const __nv_bfloat16 hx = __float2bfloat16(v.x), hy = __float2bfloat16(v.y);
    const __nv_bfloat16 hz = __float2bfloat16(v.z), hw = __float2bfloat16(v.w);
    uint2 hi, lo;
    hi.x = bf2u(__nv_bfloat162(hx, hy));
    hi.y = bf2u(__nv_bfloat162(hz, hw));
    lo.x = bf2u(__floats2bfloat162_rn(v.x - __bfloat162float(hx),
                                      v.y - __bfloat162float(hy)));
    lo.y = bf2u(__floats2bfloat162_rn(v.z - __bfloat162float(hz),
                                      v.w - __bfloat162float(hw)));
    reinterpret_cast<uint2*>(g_xhi)[idx] = hi;
    reinterpret_cast<uint2*>(g_xlo)[idx] = lo;

    if (idx < OUT_DIM * 16) {
        const float m = means[idx];
        const __nv_bfloat16 h = __float2bfloat16(m);
        const __nv_bfloat16 l = __float2bfloat16(m - __bfloat162float(h));
        g_mhl[idx] = (uint32_t)bfbits(h) | ((uint32_t)bfbits(l) << 16);
    }
}

// ---------------------------------------------------------------------------
// Main: cp.async x tiles + batched W gather (PRMT unpack) -> mma.sync 3-pass
// -> partials -> per-o-tile counter; 8th arriver reduces its tile + bias.
// ---------------------------------------------------------------------------
__global__ void __launch_bounds__(THREADS, 1)
sic_mma(const float* __restrict__ bias, const int* __restrict__ dest,
        float* __restrict__ out)
{
    extern __shared__ __align__(16) char smem[];
    __shared__ int s_red;
    const uint32_t sb = smem_u32(smem);
    const int tid = threadIdx.x;
    const int wid = tid >> 5, lid = tid & 31;
    const int ks  = blockIdx.x & (KSPLIT - 1);
    const int oy  = blockIdx.x >> 3;
    const int o0  = oy * N_TILE;
    const int k0  = ks * K_TILE;

    // ---- x tile copy via cp.async: 2048 16B-chunks per plane ----
#pragma unroll
    for (int p = 0; p < 4; p++) {
        const int c   = tid + p * THREADS;       // 0..2047
        const int row = c >> 4;
        const int ci  = c & 15;
        const size_t goff = (size_t)row * IN_DIM + k0 + ci * 8;   // elems
        CP_ASYNC16(sb + XS_HI + row * ROW_B + ci * 16, (const char*)(g_xhi + goff));
        CP_ASYNC16(sb + XS_LO + row * ROW_B + ci * 16, (const char*)(g_xlo + goff));
    }
    CP_COMMIT();

    // ---- W gather, batched: 4 int4 dest loads -> 16 mhl loads -> PRMT ----
    {
        int4 dd[4];
#pragma unroll
        for (int j = 0; j < 4; j++) {
            const int s = tid + j * THREADS;     // 0..2047
            const int o = s >> 5;
            const int kq = s & 31;
            dd[j] = reinterpret_cast<const int4*>(dest)
                        [(size_t)(o0 + o) * (IN_DIM / 4) + (k0 >> 2) + kq];
        }
        uint32_t m[4][4];
#pragma unroll
        for (int j = 0; j < 4; j++) {
            m[j][0] = g_mhl[dd[j].x]; m[j][1] = g_mhl[dd[j].y];
            m[j][2] = g_mhl[dd[j].z]; m[j][3] = g_mhl[dd[j].w];
        }
#pragma unroll
        for (int j = 0; j < 4; j++) {
            const int s = tid + j * THREADS;
            const int o = s >> 5;
            const int kq = s & 31;
            uint2 hi, lo;
            hi.x = __byte_perm(m[j][0], m[j][1], 0x5410);
            hi.y = __byte_perm(m[j][2], m[j][3], 0x5410);
            lo.x = __byte_perm(m[j][0], m[j][1], 0x7632);
            lo.y = __byte_perm(m[j][2], m[j][3], 0x7632);
            *reinterpret_cast<uint2*>(smem + WS_HI + o * ROW_B + kq * 8) = hi;
            *reinterpret_cast<uint2*>(smem + WS_LO + o * ROW_B + kq * 8) = lo;
        }
    }
    CP_WAIT0();
    __syncthreads();

    // ---- mma.sync mainloop: warp = 16 batches x 32 outputs ----
    const int m0 = (wid & 7) * 16;
    const int nh = wid >> 3;
    float acc[4][4];
#pragma unroll
    for (int n = 0; n < 4; n++)
#pragma unroll
        for (int i = 0; i < 4; i++) acc[n][i] = 0.f;

    const uint32_t a_row  = (uint32_t)(m0 + (lid & 15)) * ROW_B;
    const uint32_t a_coff = (uint32_t)(lid >> 4) * 16;
    const uint32_t b_row  = (uint32_t)(lid & 7) * ROW_B;
    const uint32_t b_coff = (uint32_t)(lid >> 3) * 16;

#pragma unroll
    for (int kp = 0; kp < 4; kp++) {
        uint32_t ah0[4], ah1[4], al0[4], al1[4];
        {
            const uint32_t c0 = (uint32_t)(kp * 64) + a_coff;
            const uint32_t c1 = c0 + 32;
            LDSM_X4(ah0[0], ah0[1], ah0[2], ah0[3], sb + XS_HI + a_row + c0);
            LDSM_X4(ah1[0], ah1[1], ah1[2], ah1[3], sb + XS_HI + a_row + c1);
            LDSM_X4(al0[0], al0[1], al0[2], al0[3], sb + XS_LO + a_row + c0);
            LDSM_X4(al1[0], al1[1], al1[2], al1[3], sb + XS_LO + a_row + c1);
        }
#pragma unroll
        for (int n = 0; n < 4; n++) {
            const uint32_t bbase = (uint32_t)((nh * 4 + n) * 8) * ROW_B
                                 + (uint32_t)(kp * 64) + b_coff;
            uint32_t bh[4], bl[4];
            LDSM_X4(bh[0], bh[1], bh[2], bh[3], sb + WS_HI + b_row + bbase);
            LDSM_X4(bl[0], bl[1], bl[2], bl[3], sb + WS_LO + b_row + bbase);
            MMA_BF16(acc[n], ah0[0], ah0[1], ah0[2], ah0[3], bh[0], bh[1]);
            MMA_BF16(acc[n], al0[0], al0[1], al0[2], al0[3], bh[0], bh[1]);
            MMA_BF16(acc[n], ah0[0], ah0[1], ah0[2], ah0[3], bl[0], bl[1]);
            MMA_BF16(acc[n], ah1[0], ah1[1], ah1[2], ah1[3], bh[2], bh[3]);
            MMA_BF16(acc[n], al1[0], al1[1], al1[2], al1[3], bh[2], bh[3]);
            MMA_BF16(acc[n], ah1[0], ah1[1], ah1[2], ah1[3], bl[2], bl[3]);
        }
    }

    // ---- write partials ----
    {
        const int g  = lid >> 2;
        const int tg = lid & 3;
        float* r0 = g_part + ((size_t)(ks * B_DIM + m0 + g))     * OUT_DIM
                  + o0 + nh * 32 + 2 * tg;
        float* r1 = g_part + ((size_t)(ks * B_DIM + m0 + g + 8)) * OUT_DIM
                  + o0 + nh * 32 + 2 * tg;
#pragma unroll
        for (int n = 0; n < 4; n++) {
            *reinterpret_cast<float2*>(r0 + n * 8) = make_float2(acc[n][0], acc[n][1]);
            *reinterpret_cast<float2*>(r1 + n * 8) = make_float2(acc[n][2], acc[n][3]);
        }
    }

    // ---- per-o-tile completion: 8th arriver reduces this tile ----
    __threadfence();
    __syncthreads();
    if (tid == 0) {
        const unsigned v = atomicAdd(&g_done[oy], 1u) + 1u;
        s_red = ((v & 7u) == 0u) ? 1 : 0;
    }
    __syncthreads();
    if (s_red) {
        __threadfence();
#pragma unroll 2
        for (int idx = tid; idx < B_DIM * (N_TILE / 2); idx += THREADS) {
            const int b  = idx >> 5;
            const int oo = (idx & 31) * 2;
            const float* p = g_part + (size_t)b * OUT_DIM + o0 + oo;
            float2 a = make_float2(0.f, 0.f);
#pragma unroll
            for (int k = 0; k < KSPLIT; k++) {
                const float2 v = *reinterpret_cast<const float2*>(
                    p + (size_t)k * (B_DIM * OUT_DIM));
                a.x += v.x; a.y += v.y;
            }
            const float2 bb = *reinterpret_cast<const float2*>(bias + o0 + oo);
            a.x += bb.x; a.y += bb.y;
            *reinterpret_cast<float2*>(out + (size_t)b * OUT_DIM + o0 + oo) = a;
        }
    }
}

extern "C" void kernel_launch(void* const* d_in, const int* in_sizes, int n_in,
                              void* d_out, int out_size)
{
    (void)in_sizes; (void)n_in; (void)out_size;
    const float* x     = (const float*)d_in[0];   // [128,1024] f32
    const float* means = (const float*)d_in[1];   // [1024,16]  f32
    const float* bias  = (const float*)d_in[2];   // [1024]     f32
    // d_in[3] = col_idx (identity layout per row; unused)
    const int*   dest  = (const int*)d_in[4];     // [1024*1024] i32

    cudaFuncSetAttribute(sic_mma, cudaFuncAttributeMaxDynamicSharedMemorySize,
                         SMEM_BYTES);
    sic_prep<<<128, 256>>>(x, means);
    sic_mma<<<GRID, THREADS, SMEM_BYTES>>>(bias, dest, (float*)d_out);
}

// round 13
// speedup vs baseline: 2.0596x; 1.1613x over previous
#include <cuda_runtime.h>
#include <cuda_bf16.h>
#include <cstdint>
#include <cstring>

typedef unsigned long long ull;

#define B_DIM    128
#define IN_DIM   1024
#define OUT_DIM  1024
#define KSPLIT   8
#define K_TILE   128
#define N_TILE   64
#define THREADS  512
#define GRID     (KSPLIT * (OUT_DIM / N_TILE))   // 128 CTAs, one wave

#define K_PAD    136                              // bf16 elems/row; 272B stride
#define ROW_B    (K_PAD * 2)                      // 272
#define XS_HI    0
#define XS_LO    (B_DIM * ROW_B)                  // 34816
#define WS_HI    (2 * B_DIM * ROW_B)              // 69632
#define WS_LO    (WS_HI + N_TILE * ROW_B)         // 87040
#define S_MHL    (WS_LO + N_TILE * ROW_B)         // 104448: packed means table
#define SMEM_BYTES (S_MHL + N_TILE * 16 * 4)      // 108544

// partials + per-o-tile counters (static device mem; monotonic = replay-safe)
__device__ float g_part[KSPLIT * B_DIM * OUT_DIM];               // 4 MB
__device__ unsigned g_done[OUT_DIM / N_TILE];

__device__ __forceinline__ uint32_t smem_u32(const void* p) {
    uint32_t a;
    asm("{ .reg .u64 t; cvta.to.shared.u64 t, %1; cvt.u32.u64 %0, t; }"
        : "=r"(a) : "l"(p));
    return a;
}
__device__ __forceinline__ uint32_t bf2u(__nv_bfloat162 v) {
    uint32_t u; memcpy(&u, &v, 4); return u;
}
__device__ __forceinline__ unsigned short bfbits(__nv_bfloat16 v) {
    unsigned short u; memcpy(&u, &v, 2); return u;
}

#define LDSM_X4(r0, r1, r2, r3, addr)                                       \
    asm volatile("ldmatrix.sync.aligned.m8n8.x4.shared.b16 {%0,%1,%2,%3}, [%4];" \
                 : "=r"(r0), "=r"(r1), "=r"(r2), "=r"(r3) : "r"(addr))

#define MMA_BF16(c, a0, a1, a2, a3, b0, b1)                                 \
    asm volatile("mma.sync.aligned.m16n8k16.row.col.f32.bf16.bf16.f32 "     \
                 "{%0,%1,%2,%3}, {%4,%5,%6,%7}, {%8,%9}, {%0,%1,%2,%3};"    \
                 : "+f"((c)[0]), "+f"((c)[1]), "+f"((c)[2]), "+f"((c)[3])   \
                 : "r"(a0), "r"(a1), "r"(a2), "r"(a3), "r"(b0), "r"(b1))

// ---------------------------------------------------------------------------
// Single fused kernel:
//  dest loads (first, DRAM) -> smem means table -> x hi/lo staging ->
//  W gather via LDS table + PRMT -> mma.sync 3-pass -> partials ->
//  per-tile barrier (all 8 CTAs) -> distributed 1/8-slice reduce + bias.
// ---------------------------------------------------------------------------
__global__ void __launch_bounds__(THREADS, 1)
sic_mma(const float* __restrict__ x, const float* __restrict__ means,
        const float* __restrict__ bias, const int* __restrict__ dest,
        float* __restrict__ out)
{
    extern __shared__ __align__(16) char smem[];
    const uint32_t sb = smem_u32(smem);
    uint32_t* mhl = reinterpret_cast<uint32_t*>(smem + S_MHL);
    const int tid = threadIdx.x;
    const int wid = tid >> 5, lid = tid & 31;
    const int ks  = blockIdx.x & (KSPLIT - 1);
    const int oy  = blockIdx.x >> 3;
    const int o0  = oy * N_TILE;
    const int k0  = ks * K_TILE;

    // ---- 1. dest loads FIRST (DRAM latency covers all staging below) ----
    int4 dd[4];
#pragma unroll
    for (int j = 0; j < 4; j++) {
        const int s = tid + j * THREADS;     // 0..2047
        const int o = s >> 5;
        const int kq = s & 31;
        dd[j] = reinterpret_cast<const int4*>(dest)
                    [(size_t)(o0 + o) * (IN_DIM / 4) + (k0 >> 2) + kq];
    }

    // ---- 2. means slice -> packed hi|lo smem table (1024 entries) ----
#pragma unroll
    for (int j = 0; j < 2; j++) {
        const int i = tid + j * THREADS;     // 0..1023
        const float m = means[o0 * 16 + i];
        const __nv_bfloat16 h = __float2bfloat16(m);
        const __nv_bfloat16 l = __float2bfloat16(m - __bfloat162float(h));
        mhl[i] = (uint32_t)bfbits(h) | ((uint32_t)bfbits(l) << 16);
    }

    // ---- 3. x slice [128 x 128] -> bf16 hi/lo planes (R9-proven) ----
    for (int idx = tid; idx < B_DIM * (K_TILE / 4); idx += THREADS) {
        const int row = idx >> 5;
        const int k   = (idx & 31) << 2;
        const float4 v = *reinterpret_cast<const float4*>(x + (size_t)row * IN_DIM + k0 + k);
        const __nv_bfloat16 hx = __float2bfloat16(v.x), hy = __float2bfloat16(v.y);
        const __nv_bfloat16 hz = __float2bfloat16(v.z), hw = __float2bfloat16(v.w);
        uint2 hi, lo;
        hi.x = bf2u(__nv_bfloat162(hx, hy));
        hi.y = bf2u(__nv_bfloat162(hz, hw));
        lo.x = bf2u(__floats2bfloat162_rn(v.x - __bfloat162float(hx),
                                          v.y - __bfloat162float(hy)));
        lo.y = bf2u(__floats2bfloat162_rn(v.z - __bfloat162float(hz),
                                          v.w - __bfloat162float(hw)));
        const uint32_t byte = (uint32_t)row * ROW_B + k * 2;
        *reinterpret_cast<uint2*>(smem + XS_HI + byte) = hi;
        *reinterpret_cast<uint2*>(smem + XS_LO + byte) = lo;
    }
    __syncthreads();   // means table ready

    // ---- 4. W gather: LDS table lookups + PRMT split, store planes ----
    {
        const int tbase = o0 * 16;
        uint32_t m[4][4];
#pragma unroll
        for (int j = 0; j < 4; j++) {
            m[j][0] = mhl[dd[j].x - tbase]; m[j][1] = mhl[dd[j].y - tbase];
            m[j][2] = mhl[dd[j].z - tbase]; m[j][3] = mhl[dd[j].w - tbase];
        }
#pragma unroll
        for (int j = 0; j < 4; j++) {
            const int s = tid + j * THREADS;
            const int o = s >> 5;
            const int kq = s & 31;
            uint2 hi, lo;
            hi.x = __byte_perm(m[j][0], m[j][1], 0x5410);
            hi.y = __byte_perm(m[j][2], m[j][3], 0x5410);
            lo.x = __byte_perm(m[j][0], m[j][1], 0x7632);
            lo.y = __byte_perm(m[j][2], m[j][3], 0x7632);
            *reinterpret_cast<uint2*>(smem + WS_HI + o * ROW_B + kq * 8) = hi;
            *reinterpret_cast<uint2*>(smem + WS_LO + o * ROW_B + kq * 8) = lo;
        }
    }
    __syncthreads();

    // ---- 5. mma.sync mainloop: warp = 16 batches x 32 outputs ----
    const int m0 = (wid & 7) * 16;
    const int nh = wid >> 3;
    float acc[4][4];
#pragma unroll
    for (int n = 0; n < 4; n++)
#pragma unroll
        for (int i = 0; i < 4; i++) acc[n][i] = 0.f;

    const uint32_t a_row  = (uint32_t)(m0 + (lid & 15)) * ROW_B;
    const uint32_t a_coff = (uint32_t)(lid >> 4) * 16;
    const uint32_t b_row  = (uint32_t)(lid & 7) * ROW_B;
    const uint32_t b_coff = (uint32_t)(lid >> 3) * 16;

#pragma unroll
    for (int kp = 0; kp < 4; kp++) {
        uint32_t ah0[4], ah1[4], al0[4], al1[4];
        {
            const uint32_t c0 = (uint32_t)(kp * 64) + a_coff;
            const uint32_t c1 = c0 + 32;
            LDSM_X4(ah0[0], ah0[1], ah0[2], ah0[3], sb + XS_HI + a_row + c0);
            LDSM_X4(ah1[0], ah1[1], ah1[2], ah1[3], sb + XS_HI + a_row + c1);
            LDSM_X4(al0[0], al0[1], al0[2], al0[3], sb + XS_LO + a_row + c0);
            LDSM_X4(al1[0], al1[1], al1[2], al1[3], sb + XS_LO + a_row + c1);
        }
#pragma unroll
        for (int n = 0; n < 4; n++) {
            const uint32_t bbase = (uint32_t)((nh * 4 + n) * 8) * ROW_B
                                 + (uint32_t)(kp * 64) + b_coff;
            uint32_t bh[4], bl[4];
            LDSM_X4(bh[0], bh[1], bh[2], bh[3], sb + WS_HI + b_row + bbase);
            LDSM_X4(bl[0], bl[1], bl[2], bl[3], sb + WS_LO + b_row + bbase);
            MMA_BF16(acc[n], ah0[0], ah0[1], ah0[2], ah0[3], bh[0], bh[1]);
            MMA_BF16(acc[n], al0[0], al0[1], al0[2], al0[3], bh[0], bh[1]);
            MMA_BF16(acc[n], ah0[0], ah0[1], ah0[2], ah0[3], bl[0], bl[1]);
            MMA_BF16(acc[n], ah1[0], ah1[1], ah1[2], ah1[3], bh[2], bh[3]);
            MMA_BF16(acc[n], al1[0], al1[1], al1[2], al1[3], bh[2], bh[3]);
            MMA_BF16(acc[n], ah1[0], ah1[1], ah1[2], ah1[3], bl[2], bl[3]);
        }
    }

    // ---- 6. write partials ----
    {
        const int g  = lid >> 2;
        const int tg = lid & 3;
        float* r0 = g_part + ((size_t)(ks * B_DIM + m0 + g))     * OUT_DIM
                  + o0 + nh * 32 + 2 * tg;
        float* r1 = g_part + ((size_t)(ks * B_DIM + m0 + g + 8)) * OUT_DIM
                  + o0 + nh * 32 + 2 * tg;
#pragma unroll
        for (int n = 0; n < 4; n++) {
            *reinterpret_cast<float2*>(r0 + n * 8) = make_float2(acc[n][0], acc[n][1]);
            *reinterpret_cast<float2*>(r1 + n * 8) = make_float2(acc[n][2], acc[n][3]);
        }
    }

    // ---- 7. per-tile barrier: all 8 CTAs spin (monotonic, replay-safe) ----
    __threadfence();
    __syncthreads();
    if (tid == 0) {
        const unsigned v = atomicAdd(&g_done[oy], 1u) + 1u;
        const unsigned target = ((v - 1u) / (unsigned)KSPLIT + 1u) * (unsigned)KSPLIT;
        while (*(volatile unsigned*)&g_done[oy] < target) { }
    }
    __syncthreads();
    __threadfence();

    // ---- 8. distributed reduce: CTA ks owns batches ks*16..+15 (1 f2/thr) ----
    {
        const int b  = ks * 16 + (tid >> 5);
        const int oo = (tid & 31) * 2;
        const float* p = g_part + (size_t)b * OUT_DIM + o0 + oo;
        float2 a = make_float2(0.f, 0.f);
#pragma unroll
        for (int k = 0; k < KSPLIT; k++) {
            const float2 v = *reinterpret_cast<const float2*>(
                p + (size_t)k * (B_DIM * OUT_DIM));
            a.x += v.x; a.y += v.y;
        }
        const float2 bb = *reinterpret_cast<const float2*>(bias + o0 + oo);
        a.x += bb.x; a.y += bb.y;
        *reinterpret_cast<float2*>(out + (size_t)b * OUT_DIM + o0 + oo) = a;
    }
}

extern "C" void kernel_launch(void* const* d_in, const int* in_sizes, int n_in,
                              void* d_out, int out_size)
{
    (void)in_sizes; (void)n_in; (void)out_size;
    const float* x     = (const float*)d_in[0];   // [128,1024] f32
    const float* means = (const float*)d_in[1];   // [1024,16]  f32
    const float* bias  = (const float*)d_in[2];   // [1024]     f32
    // d_in[3] = col_idx (identity layout per row; unused)
    const int*   dest  = (const int*)d_in[4];     // [1024*1024] i32

    cudaFuncSetAttribute(sic_mma, cudaFuncAttributeMaxDynamicSharedMemorySize,
                         SMEM_BYTES);
    sic_mma<<<GRID, THREADS, SMEM_BYTES>>>(x, means, bias, dest, (float*)d_out);
}